// round 8
// baseline (speedup 1.0000x reference)
#include <cuda_runtime.h>

#define N_NODES 100000
#define N_EDGES 800000
#define DIN 16
#define H 128
#define OUTD 3
#define SLOPE 0.01f

// ---------------- scratch (no allocations allowed) ----------------
__device__ __align__(16) float g_deg[N_NODES];        // in-degree (float)
__device__ __align__(16) float g_dinv[N_NODES];       // rsqrt(deg+1)
__device__ __align__(16) float g_z  [N_NODES * 3];    // x1 @ Wc
__device__ __align__(16) float g_z1 [N_NODES * 3];    // A @ z
__device__ __align__(16) float g_out[N_NODES * 3];    // final accumulation (scratch)
__device__ __align__(16) float g_a1 [N_NODES];        // A @ ones
__device__ __align__(16) float g_U  [H * OUTD];       // W2 @ W_out
__device__ __align__(16) float g_Wc [H * OUTD];       // W1 @ U
__device__ float g_v[OUTD];                           // b1 @ U
__device__ float g_c[OUTD];                           // b2 @ W_out + b_out

// resolved by k_ident (stream order = visibility for later kernels)
__device__ const void*  g_ei_ptr;                     // edge_index [2, E]
__device__ int          g_ei64;                       // 1 = int64 elements, 0 = int32
__device__ const float* g_feat_p;                     // feature    [N, DIN]

// ---------------- input identification (dtype- and order-robust) ----------
// Sample int32 WORDS (in-bounds for either dtype: >=1.6M words exist).
//  edge_index(int32): every word is an index in [0, N)           -> edge, !is64
//  edge_index(int64): words alternate (index, 0); all in [0, N)  -> edge,  is64
//  feature (float32): N(0,1) bit patterns land in [0,100000) only for
//                     |f| < 1.4e-40 -> edge test fails
__global__ void k_ident(const int* A, const int* B) {
    int okA = 1, okB = 1, zA = 1, zB = 1;
    for (int j = 0; j < 256; j++) {
        int idx = j * 6247 + 2;                 // even, < 1,600,000
        if ((unsigned)A[idx]     >= N_NODES) okA = 0;
        if ((unsigned)B[idx]     >= N_NODES) okB = 0;
        if ((unsigned)A[idx + 1] >= N_NODES) okA = 0;   // odd word
        if ((unsigned)B[idx + 1] >= N_NODES) okB = 0;
        if (A[idx + 1] != 0) zA = 0;            // odd word == hi half?
        if (B[idx + 1] != 0) zB = 0;
    }
    if (okA && !okB)      { g_ei_ptr = A; g_ei64 = zA; g_feat_p = (const float*)B; }
    else if (okB && !okA) { g_ei_ptr = B; g_ei64 = zB; g_feat_p = (const float*)A; }
    else                  { g_ei_ptr = B; g_ei64 = zB; g_feat_p = (const float*)A; }
}

__device__ __forceinline__ int2 load_edge(int e) {
    if (g_ei64) {
        const long long* p = (const long long*)g_ei_ptr;
        return make_int2((int)p[e], (int)p[N_EDGES + e]);
    } else {
        const int* p = (const int*)g_ei_ptr;
        return make_int2(p[e], p[N_EDGES + e]);
    }
}

// ---------------- tiny setup kernels ----------------
__global__ void k_zero_deg() {
    int i = blockIdx.x * blockDim.x + threadIdx.x;
    if (i < N_NODES) g_deg[i] = 0.0f;
}

__global__ void k_count_deg() {
    int e = blockIdx.x * blockDim.x + threadIdx.x;
    if (e >= N_EDGES) return;
    int2 sd = load_edge(e);
    if ((unsigned)sd.y >= N_NODES) return;            // guard: never trap
    atomicAdd(&g_deg[sd.y], 1.0f);
}

__global__ void k_dinv() {
    int i = blockIdx.x * blockDim.x + threadIdx.x;
    if (i < N_NODES) g_dinv[i] = rsqrtf(g_deg[i] + 1.0f);
}

// U = W2 @ W_out   [128,3]
__global__ void k_U(const float* __restrict__ W2, const float* __restrict__ Wout) {
    __shared__ float sWo[H * OUTD];
    int t = threadIdx.x;
    for (int idx = t; idx < H * OUTD; idx += blockDim.x) sWo[idx] = Wout[idx];
    __syncthreads();
    if (t < H * OUTD) {
        int k = t / 3, o = t % 3;
        float s = 0.0f;
        #pragma unroll 8
        for (int j = 0; j < H; j++) s += W2[k * H + j] * sWo[j * 3 + o];
        g_U[t] = s;
    }
}

// Wc = W1 @ U; v = b1 @ U; c = b2 @ W_out + b_out
__global__ void k_Wc(const float* __restrict__ W1, const float* __restrict__ b1,
                     const float* __restrict__ b2, const float* __restrict__ Wout,
                     const float* __restrict__ bout) {
    __shared__ float sU[H * OUTD];
    int t = threadIdx.x;
    for (int idx = t; idx < H * OUTD; idx += blockDim.x) sU[idx] = g_U[idx];
    __syncthreads();
    if (t < H * OUTD) {
        int r = t / 3, o = t % 3;
        float s = 0.0f;
        #pragma unroll 8
        for (int k = 0; k < H; k++) s += W1[r * H + k] * sU[k * 3 + o];
        g_Wc[t] = s;
    } else if (t < H * OUTD + 3) {
        int o = t - H * OUTD;
        float s = 0.0f;
        for (int k = 0; k < H; k++) s += b1[k] * sU[k * 3 + o];
        g_v[o] = s;
    } else if (t < H * OUTD + 6) {
        int o = t - H * OUTD - 3;
        float s = 0.0f;
        for (int j = 0; j < H; j++) s += b2[j] * Wout[j * 3 + o];
        g_c[o] = s + bout[o];
    }
}

// ---------------- fused: z = LeakyReLU(F @ W_in + b_in) @ Wc ----------------
__global__ void __launch_bounds__(256)
k_feat(const float* __restrict__ Win, const float* __restrict__ bin) {
    __shared__ __align__(16) float sWin[DIN * H];
    __shared__ __align__(16) float sbin[H];
    __shared__ __align__(16) float sWc[H * OUTD];
    int t = threadIdx.x;
    for (int idx = t; idx < DIN * H; idx += blockDim.x) sWin[idx] = Win[idx];
    for (int idx = t; idx < H; idx += blockDim.x) sbin[idx] = bin[idx];
    for (int idx = t; idx < H * OUTD; idx += blockDim.x) sWc[idx] = g_Wc[idx];
    __syncthreads();

    int i = blockIdx.x * blockDim.x + t;
    if (i >= N_NODES) return;

    const float4* Fr = (const float4*)(g_feat_p + (size_t)i * DIN);
    float4 fa = Fr[0], fb = Fr[1], fc = Fr[2], fd = Fr[3];
    float f[16] = { fa.x, fa.y, fa.z, fa.w, fb.x, fb.y, fb.z, fb.w,
                    fc.x, fc.y, fc.z, fc.w, fd.x, fd.y, fd.z, fd.w };

    float acc0 = 0.0f, acc1 = 0.0f, acc2 = 0.0f;

    #pragma unroll 4
    for (int j0 = 0; j0 < H; j0 += 4) {
        float4 h = *(const float4*)&sbin[j0];
        #pragma unroll
        for (int k = 0; k < DIN; k++) {
            float4 w = *(const float4*)&sWin[k * H + j0];
            h.x = fmaf(f[k], w.x, h.x);
            h.y = fmaf(f[k], w.y, h.y);
            h.z = fmaf(f[k], w.z, h.z);
            h.w = fmaf(f[k], w.w, h.w);
        }
        h.x = h.x > 0.0f ? h.x : SLOPE * h.x;
        h.y = h.y > 0.0f ? h.y : SLOPE * h.y;
        h.z = h.z > 0.0f ? h.z : SLOPE * h.z;
        h.w = h.w > 0.0f ? h.w : SLOPE * h.w;
        const float4* wc = (const float4*)&sWc[j0 * 3];
        float4 wa = wc[0], wb = wc[1], wd = wc[2];
        acc0 = fmaf(h.x, wa.x, fmaf(h.y, wa.w, fmaf(h.z, wb.z, fmaf(h.w, wd.y, acc0))));
        acc1 = fmaf(h.x, wa.y, fmaf(h.y, wb.x, fmaf(h.z, wb.w, fmaf(h.w, wd.z, acc1))));
        acc2 = fmaf(h.x, wa.z, fmaf(h.y, wb.y, fmaf(h.z, wd.x, fmaf(h.w, wd.w, acc2))));
    }
    g_z[i * 3 + 0] = acc0;
    g_z[i * 3 + 1] = acc1;
    g_z[i * 3 + 2] = acc2;
}

// ---------------- aggregation 1: z1 = A z, a1 = A 1 ----------------
__global__ void k_init1() {
    int i = blockIdx.x * blockDim.x + threadIdx.x;
    if (i >= N_NODES) return;
    float dv = g_dinv[i];
    float d2 = dv * dv;
    g_z1[3 * i + 0] = d2 * g_z[3 * i + 0];
    g_z1[3 * i + 1] = d2 * g_z[3 * i + 1];
    g_z1[3 * i + 2] = d2 * g_z[3 * i + 2];
    g_a1[i] = d2;
}

__global__ void k_scatter1() {
    int e = blockIdx.x * blockDim.x + threadIdx.x;
    if (e >= N_EDGES) return;
    int2 sd = load_edge(e);
    if ((unsigned)sd.x >= N_NODES || (unsigned)sd.y >= N_NODES) return;  // guard
    float w = g_dinv[sd.x] * g_dinv[sd.y];
    atomicAdd(&g_z1[3 * sd.y + 0], w * g_z[3 * sd.x + 0]);
    atomicAdd(&g_z1[3 * sd.y + 1], w * g_z[3 * sd.x + 1]);
    atomicAdd(&g_z1[3 * sd.y + 2], w * g_z[3 * sd.x + 2]);
    atomicAdd(&g_a1[sd.y], w);
}

// ---------------- aggregation 2 into scratch g_out ----------------
__global__ void k_init2() {
    int i = blockIdx.x * blockDim.x + threadIdx.x;
    if (i >= N_NODES) return;
    float dv = g_dinv[i];
    float d2 = dv * dv;
    float a = g_a1[i];
    g_out[3 * i + 0] = d2 * g_z1[3 * i + 0] + a * g_v[0] + g_c[0];
    g_out[3 * i + 1] = d2 * g_z1[3 * i + 1] + a * g_v[1] + g_c[1];
    g_out[3 * i + 2] = d2 * g_z1[3 * i + 2] + a * g_v[2] + g_c[2];
}

__global__ void k_scatter2() {
    int e = blockIdx.x * blockDim.x + threadIdx.x;
    if (e >= N_EDGES) return;
    int2 sd = load_edge(e);
    if ((unsigned)sd.x >= N_NODES || (unsigned)sd.y >= N_NODES) return;  // guard
    float w = g_dinv[sd.x] * g_dinv[sd.y];
    atomicAdd(&g_out[3 * sd.y + 0], w * g_z1[3 * sd.x + 0]);
    atomicAdd(&g_out[3 * sd.y + 1], w * g_z1[3 * sd.x + 1]);
    atomicAdd(&g_out[3 * sd.y + 2], w * g_z1[3 * sd.x + 2]);
}

// ---------------- final: plain coalesced copy g_out -> d_out ----------------
__global__ void k_final(float* __restrict__ out) {
    int i = blockIdx.x * blockDim.x + threadIdx.x;   // float4 index
    const int n4 = (N_NODES * 3) / 4;                // 75000 exact
    if (i < n4) ((float4*)out)[i] = ((const float4*)g_out)[i];
}

// ---------------- launch ----------------
extern "C" void kernel_launch(void* const* d_in, const int* in_sizes, int n_in,
                              void* d_out, int out_size) {
    // ---- size-based scan ----
    const void* cand16[2] = {0, 0}; int n16 = 0;      // feature / edge_index
    const float* W16k[2]  = {0, 0}; int nW  = 0;      // the two 128x128 mats, in order
    const float* b128[3]  = {0, 0, 0}; int nb = 0;    // biases (all zero here)
    const float* Win  = 0;
    const float* Wout = 0;
    const float* bout = 0;
    int pos3 = -1;

    for (int i = 0; i < n_in; i++) {
        switch (in_sizes[i]) {
            case 1600000: if (n16 < 2) cand16[n16++] = d_in[i]; break;
            case 800000:  /* edge_type — unused */              break;
            case 2048:    Win  = (const float*)d_in[i];         break;
            case 16384:   if (nW < 2) W16k[nW++] = (const float*)d_in[i]; break;
            case 384:     Wout = (const float*)d_in[i];         break;
            case 128:     if (nb < 3) b128[nb++] = (const float*)d_in[i]; break;
            case 3:       bout = (const float*)d_in[i]; pos3 = i; break;
            default: break;
        }
    }

    // order convention: if b_out (unique size 3) comes first, order is reversed
    const float* W1;
    const float* W2;
    if (pos3 == 0) { W2 = W16k[0]; W1 = W16k[1]; }
    else           { W1 = W16k[0]; W2 = W16k[1]; }

    // fallback to dict order if the scan found anything unexpected
    if (n16 < 2 || nW < 2 || nb < 3 || !Win || !Wout || !bout) {
        cand16[0] = d_in[0]; cand16[1] = d_in[1];
        Win = (const float*)d_in[3]; b128[0] = (const float*)d_in[4];
        W1  = (const float*)d_in[5]; b128[1] = (const float*)d_in[6];
        W2  = (const float*)d_in[7]; b128[2] = (const float*)d_in[8];
        Wout = (const float*)d_in[9]; bout = (const float*)d_in[10];
    }
    const float* bin = b128[0];
    const float* b1  = b128[1];
    const float* b2  = b128[2];
    float* out = (float*)d_out;

    const int TB = 256;
    const int GN = (N_NODES + TB - 1) / TB;            // 391
    const int GE = (N_EDGES + TB - 1) / TB;            // 3125
    const int G4 = (N_NODES * 3 / 4 + TB - 1) / TB;    // 293

    k_ident<<<1, 1>>>((const int*)cand16[0], (const int*)cand16[1]);

    k_zero_deg<<<GN, TB>>>();
    k_count_deg<<<GE, TB>>>();
    k_dinv<<<GN, TB>>>();

    k_U<<<1, 384>>>(W2, Wout);
    k_Wc<<<1, 416>>>(W1, b1, b2, Wout, bout);

    k_feat<<<GN, TB>>>(Win, bin);

    k_init1<<<GN, TB>>>();
    k_scatter1<<<GE, TB>>>();

    k_init2<<<GN, TB>>>();
    k_scatter2<<<GE, TB>>>();

    k_final<<<G4, TB>>>(out);
}

// round 9
// speedup vs baseline: 1.2544x; 1.2544x over previous
#include <cuda_runtime.h>

#define N_NODES 100000
#define N_EDGES 800000
#define DIN 16
#define H 128
#define OUTD 3
#define SLOPE 0.01f

// ---------------- scratch (no allocations allowed) ----------------
__device__ __align__(16) float g_deg[N_NODES];        // in-degree (float)
__device__ __align__(16) float g_dinv[N_NODES];       // rsqrt(deg+1)
__device__ __align__(16) float g_z  [N_NODES * 3];    // x1 @ Wc
__device__ __align__(16) float g_z1 [N_NODES * 3];    // edge-accumulator, then A@z
__device__ __align__(16) float g_a1 [N_NODES];        // edge-accumulator, then A@1
__device__ __align__(16) float g_w  [N_EDGES];        // per-edge weight dinv_s*dinv_d
__device__ __align__(16) float g_Wc [H * OUTD];       // W1 @ W2 @ W_out
__device__ float g_v[OUTD];                           // b1 @ W2 @ W_out
__device__ float g_c[OUTD];                           // b2 @ W_out + b_out

// resolved by ident phase (stream order = visibility for later kernels)
__device__ const void*  g_ei_ptr;                     // edge_index [2, E]
__device__ int          g_ei64;                       // 1 = int64 elements, 0 = int32
__device__ const float* g_feat_p;                     // feature    [N, DIN]

__device__ __forceinline__ int2 load_edge(int e) {
    if (g_ei64) {
        const long long* p = (const long long*)g_ei_ptr;
        return make_int2((int)p[e], (int)p[N_EDGES + e]);
    } else {
        const int* p = (const int*)g_ei_ptr;
        return make_int2(p[e], p[N_EDGES + e]);
    }
}

// ---------------- K1: zero accumulators + content-based input ident --------
// ident: sample int32 WORDS (in-bounds for either dtype).
//  edge_index(int32): every word in [0, N)                      -> edge, !is64
//  edge_index(int64): words alternate (index, 0), all in [0, N) -> edge,  is64
//  feature (float32): N(0,1) bits land in [0,100000) only for |f|<1.4e-40
__global__ void k_init(const int* A, const int* B) {
    int i = blockIdx.x * blockDim.x + threadIdx.x;
    if (i < N_NODES) {
        g_deg[i] = 0.0f;
        g_a1[i]  = 0.0f;
        g_z1[3 * i + 0] = 0.0f;
        g_z1[3 * i + 1] = 0.0f;
        g_z1[3 * i + 2] = 0.0f;
    }
    if (blockIdx.x == 0) {
        __shared__ int flags[4];                      // okA, okB, zA, zB
        int t = threadIdx.x;
        if (t < 4) flags[t] = 1;
        __syncthreads();
        if (t < 256) {
            int idx = t * 6247 + 2;                   // even, < 1,600,000
            int a0 = A[idx], a1v = A[idx + 1];
            int b0 = B[idx], b1v = B[idx + 1];
            if ((unsigned)a0 >= N_NODES || (unsigned)a1v >= N_NODES) atomicAnd(&flags[0], 0);
            if ((unsigned)b0 >= N_NODES || (unsigned)b1v >= N_NODES) atomicAnd(&flags[1], 0);
            if (a1v != 0) atomicAnd(&flags[2], 0);
            if (b1v != 0) atomicAnd(&flags[3], 0);
        }
        __syncthreads();
        if (t == 0) {
            if (flags[0] && !flags[1]) { g_ei_ptr = A; g_ei64 = flags[2]; g_feat_p = (const float*)B; }
            else                       { g_ei_ptr = B; g_ei64 = flags[3]; g_feat_p = (const float*)A; }
        }
    }
}

// ---------------- K2: edge degree count + constant-chain block --------------
// blocks [0, nEdgeBlocks): degree atomics. block nEdgeBlocks: U -> Wc, v, c.
__global__ void __launch_bounds__(384)
k_count(int nEdgeBlocks,
        const float* __restrict__ W1, const float* __restrict__ W2,
        const float* __restrict__ Wout,
        const float* __restrict__ b1, const float* __restrict__ b2,
        const float* __restrict__ bout) {
    if (blockIdx.x < (unsigned)nEdgeBlocks) {
        int e = blockIdx.x * 384 + threadIdx.x;
        if (e >= N_EDGES) return;
        int2 sd = load_edge(e);
        if ((unsigned)sd.y >= N_NODES) return;        // guard: never trap
        atomicAdd(&g_deg[sd.y], 1.0f);
        return;
    }
    // ---- constants block: U = W2@Wout ; Wc = W1@U ; v = b1@U ; c = b2@Wout+bout
    __shared__ float sWo[H * OUTD];
    __shared__ float sU [H * OUTD];
    int t = threadIdx.x;
    sWo[t] = Wout[t];                                 // t < 384 exactly
    __syncthreads();
    {                                                  // phase 1: U
        int k = t / 3, o = t % 3;
        float s = 0.0f;
        #pragma unroll 8
        for (int j = 0; j < H; j++) s = fmaf(W2[k * H + j], sWo[j * 3 + o], s);
        sU[t] = s;
    }
    __syncthreads();
    {                                                  // phase 2: Wc
        int r = t / 3, o = t % 3;
        float s = 0.0f;
        #pragma unroll 8
        for (int k = 0; k < H; k++) s = fmaf(W1[r * H + k], sU[k * 3 + o], s);
        g_Wc[t] = s;
    }
    if (t < 3) {                                       // phase 3: v
        float s = 0.0f;
        for (int k = 0; k < H; k++) s = fmaf(b1[k], sU[k * 3 + t], s);
        g_v[t] = s;
    } else if (t < 6) {                                // phase 3: c
        int o = t - 3;
        float s = 0.0f;
        for (int j = 0; j < H; j++) s = fmaf(b2[j], sWo[j * 3 + o], s);
        g_c[o] = s + bout[o];
    }
}

// ---------------- K3: dinv + fused z = LeakyReLU(F@Win + bin) @ Wc ---------
__global__ void __launch_bounds__(256)
k_feat(const float* __restrict__ Win, const float* __restrict__ bin) {
    __shared__ __align__(16) float sWin[DIN * H];
    __shared__ __align__(16) float sbin[H];
    __shared__ __align__(16) float sWc[H * OUTD];
    int t = threadIdx.x;
    for (int idx = t; idx < DIN * H; idx += blockDim.x) sWin[idx] = Win[idx];
    for (int idx = t; idx < H; idx += blockDim.x) sbin[idx] = bin[idx];
    for (int idx = t; idx < H * OUTD; idx += blockDim.x) sWc[idx] = g_Wc[idx];
    __syncthreads();

    int i = blockIdx.x * blockDim.x + t;
    if (i >= N_NODES) return;

    g_dinv[i] = rsqrtf(g_deg[i] + 1.0f);              // absorbed k_dinv

    const float4* Fr = (const float4*)(g_feat_p + (size_t)i * DIN);
    float4 fa = Fr[0], fb = Fr[1], fc = Fr[2], fd = Fr[3];
    float f[16] = { fa.x, fa.y, fa.z, fa.w, fb.x, fb.y, fb.z, fb.w,
                    fc.x, fc.y, fc.z, fc.w, fd.x, fd.y, fd.z, fd.w };

    float acc0 = 0.0f, acc1 = 0.0f, acc2 = 0.0f;

    #pragma unroll 4
    for (int j0 = 0; j0 < H; j0 += 4) {
        float4 h = *(const float4*)&sbin[j0];
        #pragma unroll
        for (int k = 0; k < DIN; k++) {
            float4 w = *(const float4*)&sWin[k * H + j0];
            h.x = fmaf(f[k], w.x, h.x);
            h.y = fmaf(f[k], w.y, h.y);
            h.z = fmaf(f[k], w.z, h.z);
            h.w = fmaf(f[k], w.w, h.w);
        }
        h.x = h.x > 0.0f ? h.x : SLOPE * h.x;
        h.y = h.y > 0.0f ? h.y : SLOPE * h.y;
        h.z = h.z > 0.0f ? h.z : SLOPE * h.z;
        h.w = h.w > 0.0f ? h.w : SLOPE * h.w;
        const float4* wc = (const float4*)&sWc[j0 * 3];
        float4 wa = wc[0], wb = wc[1], wd = wc[2];
        acc0 = fmaf(h.x, wa.x, fmaf(h.y, wa.w, fmaf(h.z, wb.z, fmaf(h.w, wd.y, acc0))));
        acc1 = fmaf(h.x, wa.y, fmaf(h.y, wb.x, fmaf(h.z, wb.w, fmaf(h.w, wd.z, acc1))));
        acc2 = fmaf(h.x, wa.z, fmaf(h.y, wb.y, fmaf(h.z, wd.x, fmaf(h.w, wd.w, acc2))));
    }
    g_z[i * 3 + 0] = acc0;
    g_z[i * 3 + 1] = acc1;
    g_z[i * 3 + 2] = acc2;
}

// ---------------- K4: edge pass 1 -> accumulate into pre-zeroed z1/a1 ------
__global__ void k_scatter1() {
    int e = blockIdx.x * blockDim.x + threadIdx.x;
    if (e >= N_EDGES) return;
    int2 sd = load_edge(e);
    if ((unsigned)sd.x >= N_NODES || (unsigned)sd.y >= N_NODES) { g_w[e] = 0.0f; return; }
    float w = g_dinv[sd.x] * g_dinv[sd.y];
    g_w[e] = w;                                       // memoize for pass 2
    atomicAdd(&g_z1[3 * sd.y + 0], w * g_z[3 * sd.x + 0]);
    atomicAdd(&g_z1[3 * sd.y + 1], w * g_z[3 * sd.x + 1]);
    atomicAdd(&g_z1[3 * sd.y + 2], w * g_z[3 * sd.x + 2]);
    atomicAdd(&g_a1[sd.y], w);
}

// ---------------- K5: finalize z1/a1 (self-loop) + seed output -------------
// z1 := z1_acc + d2*z ; a1 := a1_acc + d2 ; out := d2*z1 + a1*v + c
__global__ void k_mid(float* __restrict__ out) {
    int i = blockIdx.x * blockDim.x + threadIdx.x;
    if (i >= N_NODES) return;
    float dv = g_dinv[i];
    float d2 = dv * dv;
    float z1x = g_z1[3 * i + 0] + d2 * g_z[3 * i + 0];
    float z1y = g_z1[3 * i + 1] + d2 * g_z[3 * i + 1];
    float z1z = g_z1[3 * i + 2] + d2 * g_z[3 * i + 2];
    g_z1[3 * i + 0] = z1x;
    g_z1[3 * i + 1] = z1y;
    g_z1[3 * i + 2] = z1z;
    float a = g_a1[i] + d2;
    out[3 * i + 0] = d2 * z1x + a * g_v[0] + g_c[0];
    out[3 * i + 1] = d2 * z1y + a * g_v[1] + g_c[1];
    out[3 * i + 2] = d2 * z1z + a * g_v[2] + g_c[2];
}

// ---------------- K6: edge pass 2 -> atomics straight into d_out -----------
__global__ void k_scatter2(float* __restrict__ out) {
    int e = blockIdx.x * blockDim.x + threadIdx.x;
    if (e >= N_EDGES) return;
    int2 sd = load_edge(e);
    if ((unsigned)sd.x >= N_NODES || (unsigned)sd.y >= N_NODES) return;
    float w = g_w[e];
    atomicAdd(&out[3 * sd.y + 0], w * g_z1[3 * sd.x + 0]);
    atomicAdd(&out[3 * sd.y + 1], w * g_z1[3 * sd.x + 1]);
    atomicAdd(&out[3 * sd.y + 2], w * g_z1[3 * sd.x + 2]);
}

// ---------------- launch ----------------
extern "C" void kernel_launch(void* const* d_in, const int* in_sizes, int n_in,
                              void* d_out, int out_size) {
    // ---- size-based scan (order-independent) ----
    const void* cand16[2] = {0, 0}; int n16 = 0;      // feature / edge_index
    const float* W16k[2]  = {0, 0}; int nW  = 0;      // 128x128 mats, in order seen
    const float* b128[3]  = {0, 0, 0}; int nb = 0;    // biases (zeros in data)
    const float* Win  = 0;
    const float* Wout = 0;
    const float* bout = 0;
    int pos3 = -1;

    for (int i = 0; i < n_in; i++) {
        switch (in_sizes[i]) {
            case 1600000: if (n16 < 2) cand16[n16++] = d_in[i]; break;
            case 800000:  /* edge_type — unused */              break;
            case 2048:    Win  = (const float*)d_in[i];         break;
            case 16384:   if (nW < 2) W16k[nW++] = (const float*)d_in[i]; break;
            case 384:     Wout = (const float*)d_in[i];         break;
            case 128:     if (nb < 3) b128[nb++] = (const float*)d_in[i]; break;
            case 3:       bout = (const float*)d_in[i]; pos3 = i; break;
            default: break;
        }
    }
    // order convention: b_out (unique size 3) first => reversed order
    const float* W1;
    const float* W2;
    if (pos3 == 0) { W2 = W16k[0]; W1 = W16k[1]; }
    else           { W1 = W16k[0]; W2 = W16k[1]; }
    if (n16 < 2 || nW < 2 || nb < 3 || !Win || !Wout || !bout) {   // dict-order fallback
        cand16[0] = d_in[0]; cand16[1] = d_in[1];
        Win = (const float*)d_in[3]; b128[0] = (const float*)d_in[4];
        W1  = (const float*)d_in[5]; b128[1] = (const float*)d_in[6];
        W2  = (const float*)d_in[7]; b128[2] = (const float*)d_in[8];
        Wout = (const float*)d_in[9]; bout = (const float*)d_in[10];
    }
    const float* bin = b128[0];
    const float* b1  = b128[1];
    const float* b2  = b128[2];
    float* out = (float*)d_out;

    const int TB  = 256;
    const int GN  = (N_NODES + TB - 1) / TB;           // 391
    const int GE  = (N_EDGES + TB - 1) / TB;           // 3125
    const int GE2 = (N_EDGES + 383) / 384;             // 2084 edge blocks @384

    k_init<<<GN, TB>>>((const int*)cand16[0], (const int*)cand16[1]);
    k_count<<<GE2 + 1, 384>>>(GE2, W1, W2, Wout, b1, b2, bout);
    k_feat<<<GN, TB>>>(Win, bin);
    k_scatter1<<<GE, TB>>>();
    k_mid<<<GN, TB>>>(out);
    k_scatter2<<<GE, TB>>>(out);
}

// round 10
// speedup vs baseline: 1.5707x; 1.2521x over previous
#include <cuda_runtime.h>

#define N_NODES 100000
#define N_EDGES 800000
#define DIN 16
#define H 128
#define OUTD 3
#define SLOPE 0.01f

// ---------------- scratch (no allocations allowed) ----------------
__device__ __align__(16) float  g_deg[N_NODES];       // in-degree (float)
__device__ __align__(16) float  g_dinv[N_NODES];      // rsqrt(deg+1)
__device__ __align__(16) float4 g_z4 [N_NODES];       // (x1@Wc, pad)
__device__ __align__(16) float4 g_acc[N_NODES];       // pass-1 acc (wz,w); reused pass-2
__device__ __align__(16) float4 g_z14[N_NODES];       // finalized hop-1 (z1, pad)
__device__ __align__(16) float  g_w  [N_EDGES];       // per-edge weight dinv_s*dinv_d
__device__ __align__(16) float  g_Wc [H * OUTD];      // W1 @ W2 @ W_out
__device__ float g_v[OUTD];                           // b1 @ W2 @ W_out
__device__ float g_c[OUTD];                           // b2 @ W_out + b_out

// resolved by ident phase (stream order = visibility for later kernels)
__device__ const void*  g_ei_ptr;                     // edge_index [2, E]
__device__ int          g_ei64;                       // 1 = int64 elements, 0 = int32
__device__ const float* g_feat_p;                     // feature    [N, DIN]

__device__ __forceinline__ int2 load_edge(int e) {
    if (g_ei64) {
        const long long* p = (const long long*)g_ei_ptr;
        return make_int2((int)p[e], (int)p[N_EDGES + e]);
    } else {
        const int* p = (const int*)g_ei_ptr;
        return make_int2(p[e], p[N_EDGES + e]);
    }
}

// ---------------- K1: zero accumulators + content-based input ident --------
__global__ void k_init(const int* A, const int* B) {
    int i = blockIdx.x * blockDim.x + threadIdx.x;
    if (i < N_NODES) {
        g_deg[i] = 0.0f;
        g_acc[i] = make_float4(0.0f, 0.0f, 0.0f, 0.0f);
    }
    if (blockIdx.x == 0) {
        __shared__ int flags[4];                      // okA, okB, zA, zB
        int t = threadIdx.x;
        if (t < 4) flags[t] = 1;
        __syncthreads();
        if (t < 256) {
            int idx = t * 6247 + 2;                   // even, < 1,600,000
            int a0 = A[idx], a1v = A[idx + 1];
            int b0 = B[idx], b1v = B[idx + 1];
            if ((unsigned)a0 >= N_NODES || (unsigned)a1v >= N_NODES) atomicAnd(&flags[0], 0);
            if ((unsigned)b0 >= N_NODES || (unsigned)b1v >= N_NODES) atomicAnd(&flags[1], 0);
            if (a1v != 0) atomicAnd(&flags[2], 0);
            if (b1v != 0) atomicAnd(&flags[3], 0);
        }
        __syncthreads();
        if (t == 0) {
            if (flags[0] && !flags[1]) { g_ei_ptr = A; g_ei64 = flags[2]; g_feat_p = (const float*)B; }
            else                       { g_ei_ptr = B; g_ei64 = flags[3]; g_feat_p = (const float*)A; }
        }
    }
}

// ---------------- K2: edge degree count + constant-chain block --------------
__global__ void __launch_bounds__(384)
k_count(int nEdgeBlocks,
        const float* __restrict__ W1, const float* __restrict__ W2,
        const float* __restrict__ Wout,
        const float* __restrict__ b1, const float* __restrict__ b2,
        const float* __restrict__ bout) {
    if (blockIdx.x < (unsigned)nEdgeBlocks) {
        int e = blockIdx.x * 384 + threadIdx.x;
        if (e >= N_EDGES) return;
        int2 sd = load_edge(e);
        if ((unsigned)sd.y >= N_NODES) return;        // guard: never trap
        atomicAdd(&g_deg[sd.y], 1.0f);
        return;
    }
    // constants block: U = W2@Wout ; Wc = W1@U ; v = b1@U ; c = b2@Wout+bout
    __shared__ float sWo[H * OUTD];
    __shared__ float sU [H * OUTD];
    int t = threadIdx.x;
    sWo[t] = Wout[t];                                 // t < 384 exactly
    __syncthreads();
    {                                                  // phase 1: U
        int k = t / 3, o = t % 3;
        float s = 0.0f;
        #pragma unroll 8
        for (int j = 0; j < H; j++) s = fmaf(W2[k * H + j], sWo[j * 3 + o], s);
        sU[t] = s;
    }
    __syncthreads();
    {                                                  // phase 2: Wc
        int r = t / 3, o = t % 3;
        float s = 0.0f;
        #pragma unroll 8
        for (int k = 0; k < H; k++) s = fmaf(W1[r * H + k], sU[k * 3 + o], s);
        g_Wc[t] = s;
    }
    if (t < 3) {                                       // phase 3: v
        float s = 0.0f;
        for (int k = 0; k < H; k++) s = fmaf(b1[k], sU[k * 3 + t], s);
        g_v[t] = s;
    } else if (t < 6) {                                // phase 3: c
        int o = t - 3;
        float s = 0.0f;
        for (int j = 0; j < H; j++) s = fmaf(b2[j], sWo[j * 3 + o], s);
        g_c[o] = s + bout[o];
    }
}

// ---------------- K3: dinv + fused z = LeakyReLU(F@Win + bin) @ Wc ---------
__global__ void __launch_bounds__(256)
k_feat(const float* __restrict__ Win, const float* __restrict__ bin) {
    __shared__ __align__(16) float sWin[DIN * H];
    __shared__ __align__(16) float sbin[H];
    __shared__ __align__(16) float sWc[H * OUTD];
    int t = threadIdx.x;
    for (int idx = t; idx < DIN * H; idx += blockDim.x) sWin[idx] = Win[idx];
    for (int idx = t; idx < H; idx += blockDim.x) sbin[idx] = bin[idx];
    for (int idx = t; idx < H * OUTD; idx += blockDim.x) sWc[idx] = g_Wc[idx];
    __syncthreads();

    int i = blockIdx.x * blockDim.x + t;
    if (i >= N_NODES) return;

    g_dinv[i] = rsqrtf(g_deg[i] + 1.0f);

    const float4* Fr = (const float4*)(g_feat_p + (size_t)i * DIN);
    float4 fa = Fr[0], fb = Fr[1], fc = Fr[2], fd = Fr[3];
    float f[16] = { fa.x, fa.y, fa.z, fa.w, fb.x, fb.y, fb.z, fb.w,
                    fc.x, fc.y, fc.z, fc.w, fd.x, fd.y, fd.z, fd.w };

    float acc0 = 0.0f, acc1 = 0.0f, acc2 = 0.0f;

    #pragma unroll 4
    for (int j0 = 0; j0 < H; j0 += 4) {
        float4 h = *(const float4*)&sbin[j0];
        #pragma unroll
        for (int k = 0; k < DIN; k++) {
            float4 w = *(const float4*)&sWin[k * H + j0];
            h.x = fmaf(f[k], w.x, h.x);
            h.y = fmaf(f[k], w.y, h.y);
            h.z = fmaf(f[k], w.z, h.z);
            h.w = fmaf(f[k], w.w, h.w);
        }
        h.x = h.x > 0.0f ? h.x : SLOPE * h.x;
        h.y = h.y > 0.0f ? h.y : SLOPE * h.y;
        h.z = h.z > 0.0f ? h.z : SLOPE * h.z;
        h.w = h.w > 0.0f ? h.w : SLOPE * h.w;
        const float4* wc = (const float4*)&sWc[j0 * 3];
        float4 wa = wc[0], wb = wc[1], wd = wc[2];
        acc0 = fmaf(h.x, wa.x, fmaf(h.y, wa.w, fmaf(h.z, wb.z, fmaf(h.w, wd.y, acc0))));
        acc1 = fmaf(h.x, wa.y, fmaf(h.y, wb.x, fmaf(h.z, wb.w, fmaf(h.w, wd.z, acc1))));
        acc2 = fmaf(h.x, wa.z, fmaf(h.y, wb.y, fmaf(h.z, wd.x, fmaf(h.w, wd.w, acc2))));
    }
    g_z4[i] = make_float4(acc0, acc1, acc2, 0.0f);
}

// ---------------- K4: edge pass 1 -> ONE float4 atomic per edge ------------
// acc[d] += (w*z_s, w)   — 4th lane accumulates a1 for free
__global__ void k_scatter1() {
    int e = blockIdx.x * blockDim.x + threadIdx.x;
    if (e >= N_EDGES) return;
    int2 sd = load_edge(e);
    if ((unsigned)sd.x >= N_NODES || (unsigned)sd.y >= N_NODES) { g_w[e] = 0.0f; return; }
    float w = g_dinv[sd.x] * g_dinv[sd.y];
    g_w[e] = w;                                       // memoize for pass 2
    float4 z = g_z4[sd.x];                            // single LDG.128
    atomicAdd(&g_acc[sd.y], make_float4(w * z.x, w * z.y, w * z.z, w));
}

// ---------------- K5: finalize hop-1 + reseed acc for hop-2 ----------------
// z1 = acc.xyz + d2*z ; a1 = acc.w + d2 ; acc := (d2*z1 + a1*v + c, 0)
__global__ void k_mid() {
    int i = blockIdx.x * blockDim.x + threadIdx.x;
    if (i >= N_NODES) return;
    float dv = g_dinv[i];
    float d2 = dv * dv;
    float4 acc = g_acc[i];
    float4 z   = g_z4[i];
    float z1x = acc.x + d2 * z.x;
    float z1y = acc.y + d2 * z.y;
    float z1z = acc.z + d2 * z.z;
    float a   = acc.w + d2;
    g_z14[i] = make_float4(z1x, z1y, z1z, 0.0f);
    g_acc[i] = make_float4(d2 * z1x + a * g_v[0] + g_c[0],
                           d2 * z1y + a * g_v[1] + g_c[1],
                           d2 * z1z + a * g_v[2] + g_c[2],
                           0.0f);
}

// ---------------- K6: edge pass 2 -> ONE float4 atomic per edge ------------
__global__ void k_scatter2() {
    int e = blockIdx.x * blockDim.x + threadIdx.x;
    if (e >= N_EDGES) return;
    int2 sd = load_edge(e);
    if ((unsigned)sd.x >= N_NODES || (unsigned)sd.y >= N_NODES) return;
    float w = g_w[e];
    float4 z = g_z14[sd.x];                           // single LDG.128
    atomicAdd(&g_acc[sd.y], make_float4(w * z.x, w * z.y, w * z.z, 0.0f));
}

// ---------------- K7: unpack float4 acc -> stride-3 d_out ------------------
__global__ void k_final(float* __restrict__ out) {
    int i = blockIdx.x * blockDim.x + threadIdx.x;
    if (i >= N_NODES) return;
    float4 r = g_acc[i];
    out[3 * i + 0] = r.x;
    out[3 * i + 1] = r.y;
    out[3 * i + 2] = r.z;
}

// ---------------- launch ----------------
extern "C" void kernel_launch(void* const* d_in, const int* in_sizes, int n_in,
                              void* d_out, int out_size) {
    // ---- size-based scan (order-independent) ----
    const void* cand16[2] = {0, 0}; int n16 = 0;      // feature / edge_index
    const float* W16k[2]  = {0, 0}; int nW  = 0;      // 128x128 mats, in order seen
    const float* b128[3]  = {0, 0, 0}; int nb = 0;    // biases (zeros in data)
    const float* Win  = 0;
    const float* Wout = 0;
    const float* bout = 0;
    int pos3 = -1;

    for (int i = 0; i < n_in; i++) {
        switch (in_sizes[i]) {
            case 1600000: if (n16 < 2) cand16[n16++] = d_in[i]; break;
            case 800000:  /* edge_type — unused */              break;
            case 2048:    Win  = (const float*)d_in[i];         break;
            case 16384:   if (nW < 2) W16k[nW++] = (const float*)d_in[i]; break;
            case 384:     Wout = (const float*)d_in[i];         break;
            case 128:     if (nb < 3) b128[nb++] = (const float*)d_in[i]; break;
            case 3:       bout = (const float*)d_in[i]; pos3 = i; break;
            default: break;
        }
    }
    const float* W1;
    const float* W2;
    if (pos3 == 0) { W2 = W16k[0]; W1 = W16k[1]; }    // reversed-order convention
    else           { W1 = W16k[0]; W2 = W16k[1]; }
    if (n16 < 2 || nW < 2 || nb < 3 || !Win || !Wout || !bout) {   // dict-order fallback
        cand16[0] = d_in[0]; cand16[1] = d_in[1];
        Win = (const float*)d_in[3]; b128[0] = (const float*)d_in[4];
        W1  = (const float*)d_in[5]; b128[1] = (const float*)d_in[6];
        W2  = (const float*)d_in[7]; b128[2] = (const float*)d_in[8];
        Wout = (const float*)d_in[9]; bout = (const float*)d_in[10];
    }
    const float* bin = b128[0];
    const float* b1  = b128[1];
    const float* b2  = b128[2];
    float* out = (float*)d_out;

    const int TB  = 256;
    const int GN  = (N_NODES + TB - 1) / TB;           // 391
    const int GE  = (N_EDGES + TB - 1) / TB;           // 3125
    const int GE2 = (N_EDGES + 383) / 384;             // 2084 edge blocks @384

    k_init<<<GN, TB>>>((const int*)cand16[0], (const int*)cand16[1]);
    k_count<<<GE2 + 1, 384>>>(GE2, W1, W2, Wout, b1, b2, bout);
    k_feat<<<GN, TB>>>(Win, bin);
    k_scatter1<<<GE, TB>>>();
    k_mid<<<GN, TB>>>();
    k_scatter2<<<GE, TB>>>();
    k_final<<<GN, TB>>>(out);
}

// round 11
// speedup vs baseline: 1.6120x; 1.0263x over previous
#include <cuda_runtime.h>

#define N_NODES 100000
#define N_EDGES 800000
#define DIN 16
#define H 128
#define OUTD 3
#define SLOPE 0.01f

// ---------------- scratch (no allocations; zero-initialized at load) -------
// INVARIANT: g_deg and g_acc are all-zero at kernel_launch entry; k_final
// restores this before finishing, so graph replays are deterministic.
__device__ __align__(16) float  g_deg[N_NODES];       // in-degree (float)
__device__ __align__(16) float  g_dinv[N_NODES];      // rsqrt(deg+1)
__device__ __align__(16) float4 g_z4 [N_NODES];       // p = (dinv*z, dinv)
__device__ __align__(16) float4 g_acc[N_NODES];       // edge accumulator (both passes)
__device__ __align__(16) float4 g_z14[N_NODES];       // q = (dinv*z1, 0)
__device__ __align__(16) float  g_a1 [N_NODES];       // (A·1)_d
__device__ __align__(16) float  g_Wc [H * OUTD];      // W1 @ W2 @ W_out
__device__ float g_v[OUTD];                           // b1 @ W2 @ W_out
__device__ float g_c[OUTD];                           // b2 @ W_out + b_out

// resolved by k_count block 0 (stream order = visibility for later kernels)
__device__ const void*  g_ei_ptr;                     // edge_index [2, E]
__device__ int          g_ei64;                       // 1 = int64 elements, 0 = int32
__device__ const float* g_feat_p;                     // feature    [N, DIN]

__device__ __forceinline__ int2 load_edge_g(int e) {
    if (g_ei64) {
        const long long* p = (const long long*)g_ei_ptr;
        return make_int2((int)p[e], (int)p[N_EDGES + e]);
    } else {
        const int* p = (const int*)g_ei_ptr;
        return make_int2(p[e], p[N_EDGES + e]);
    }
}

// ---------------- K1: per-block ident + degree count + constant chain ------
// ident: sample int32 WORDS (in-bounds for either dtype).
//  edge_index(int32): every word in [0, N)                      -> edge, !is64
//  edge_index(int64): words alternate (index, 0), all in [0, N) -> edge,  is64
//  feature (float32): N(0,1) bits land in [0,100000) only for |f|<1.4e-40
__global__ void __launch_bounds__(384)
k_count(int nEdgeBlocks, const int* A, const int* B,
        const float* __restrict__ W1, const float* __restrict__ W2,
        const float* __restrict__ Wout,
        const float* __restrict__ b1, const float* __restrict__ b2,
        const float* __restrict__ bout) {
    __shared__ int sflags[4];                         // okA, okB, zA, zB
    int t = threadIdx.x;
    if (t < 4) sflags[t] = 1;
    __syncthreads();
    if (t < 256) {
        int idx = t * 6247 + 2;                       // even, < 1,600,000
        int a0 = A[idx], a1v = A[idx + 1];
        int b0 = B[idx], b1v = B[idx + 1];
        if ((unsigned)a0 >= N_NODES || (unsigned)a1v >= N_NODES) atomicAnd(&sflags[0], 0);
        if ((unsigned)b0 >= N_NODES || (unsigned)b1v >= N_NODES) atomicAnd(&sflags[1], 0);
        if (a1v != 0) atomicAnd(&sflags[2], 0);
        if (b1v != 0) atomicAnd(&sflags[3], 0);
    }
    __syncthreads();
    const int*   ei;  int is64;  const float* feat;
    if (sflags[0] && !sflags[1]) { ei = A; is64 = sflags[2]; feat = (const float*)B; }
    else                         { ei = B; is64 = sflags[3]; feat = (const float*)A; }

    if (blockIdx.x == 0 && t == 0) {                  // publish for later kernels
        g_ei_ptr = ei; g_ei64 = is64; g_feat_p = feat;
    }

    if (blockIdx.x < (unsigned)nEdgeBlocks) {         // ---- degree pass ----
        int e = blockIdx.x * 384 + t;
        if (e >= N_EDGES) return;
        int d;
        if (is64) d = (int)((const long long*)ei)[N_EDGES + e];
        else      d = ei[N_EDGES + e];
        if ((unsigned)d >= N_NODES) return;           // guard: never trap
        atomicAdd(&g_deg[d], 1.0f);
        return;
    }

    // ---- constants block: U = W2@Wout ; Wc = W1@U ; v = b1@U ; c = b2@Wout+bout
    __shared__ float sWo[H * OUTD];
    __shared__ float sU [H * OUTD];
    sWo[t] = Wout[t];                                 // t < 384 exactly
    __syncthreads();
    {                                                  // phase 1: U
        int k = t / 3, o = t % 3;
        float s = 0.0f;
        #pragma unroll 8
        for (int j = 0; j < H; j++) s = fmaf(W2[k * H + j], sWo[j * 3 + o], s);
        sU[t] = s;
    }
    __syncthreads();
    {                                                  // phase 2: Wc
        int r = t / 3, o = t % 3;
        float s = 0.0f;
        #pragma unroll 8
        for (int k = 0; k < H; k++) s = fmaf(W1[r * H + k], sU[k * 3 + o], s);
        g_Wc[t] = s;
    }
    if (t < 3) {                                       // phase 3: v
        float s = 0.0f;
        for (int k = 0; k < H; k++) s = fmaf(b1[k], sU[k * 3 + t], s);
        g_v[t] = s;
    } else if (t < 6) {                                // phase 3: c
        int o = t - 3;
        float s = 0.0f;
        for (int j = 0; j < H; j++) s = fmaf(b2[j], sWo[j * 3 + o], s);
        g_c[o] = s + bout[o];
    }
}

// ---------------- K2: dinv + fused z, packed as p = (dinv*z, dinv) ---------
__global__ void __launch_bounds__(256)
k_feat(const float* __restrict__ Win, const float* __restrict__ bin) {
    __shared__ __align__(16) float sWin[DIN * H];
    __shared__ __align__(16) float sbin[H];
    __shared__ __align__(16) float sWc[H * OUTD];
    int t = threadIdx.x;
    for (int idx = t; idx < DIN * H; idx += blockDim.x) sWin[idx] = Win[idx];
    for (int idx = t; idx < H; idx += blockDim.x) sbin[idx] = bin[idx];
    for (int idx = t; idx < H * OUTD; idx += blockDim.x) sWc[idx] = g_Wc[idx];
    __syncthreads();

    int i = blockIdx.x * blockDim.x + t;
    if (i >= N_NODES) return;

    float dv = rsqrtf(g_deg[i] + 1.0f);
    g_dinv[i] = dv;

    const float4* Fr = (const float4*)(g_feat_p + (size_t)i * DIN);
    float4 fa = Fr[0], fb = Fr[1], fc = Fr[2], fd = Fr[3];
    float f[16] = { fa.x, fa.y, fa.z, fa.w, fb.x, fb.y, fb.z, fb.w,
                    fc.x, fc.y, fc.z, fc.w, fd.x, fd.y, fd.z, fd.w };

    float acc0 = 0.0f, acc1 = 0.0f, acc2 = 0.0f;

    #pragma unroll 4
    for (int j0 = 0; j0 < H; j0 += 4) {
        float4 h = *(const float4*)&sbin[j0];
        #pragma unroll
        for (int k = 0; k < DIN; k++) {
            float4 w = *(const float4*)&sWin[k * H + j0];
            h.x = fmaf(f[k], w.x, h.x);
            h.y = fmaf(f[k], w.y, h.y);
            h.z = fmaf(f[k], w.z, h.z);
            h.w = fmaf(f[k], w.w, h.w);
        }
        h.x = h.x > 0.0f ? h.x : SLOPE * h.x;
        h.y = h.y > 0.0f ? h.y : SLOPE * h.y;
        h.z = h.z > 0.0f ? h.z : SLOPE * h.z;
        h.w = h.w > 0.0f ? h.w : SLOPE * h.w;
        const float4* wc = (const float4*)&sWc[j0 * 3];
        float4 wa = wc[0], wb = wc[1], wd = wc[2];
        acc0 = fmaf(h.x, wa.x, fmaf(h.y, wa.w, fmaf(h.z, wb.z, fmaf(h.w, wd.y, acc0))));
        acc1 = fmaf(h.x, wa.y, fmaf(h.y, wb.x, fmaf(h.z, wb.w, fmaf(h.w, wd.z, acc1))));
        acc2 = fmaf(h.x, wa.z, fmaf(h.y, wb.y, fmaf(h.z, wd.x, fmaf(h.w, wd.w, acc2))));
    }
    g_z4[i] = make_float4(acc0 * dv, acc1 * dv, acc2 * dv, dv);
}

// ---------------- K3: edge pass 1 — pure gather + vector atomic ------------
__global__ void k_scatter1() {
    int e = blockIdx.x * blockDim.x + threadIdx.x;
    if (e >= N_EDGES) return;
    int2 sd = load_edge_g(e);
    if ((unsigned)sd.x >= N_NODES || (unsigned)sd.y >= N_NODES) return;
    atomicAdd(&g_acc[sd.y], g_z4[sd.x]);              // acc_d += (dinv_s*z_s, dinv_s)
}

// ---------------- K4: finalize hop 1, pack q, reset acc --------------------
// z1 = dinv*(acc.xyz + p.xyz)  (self-loop folds in);  a1 = dinv*(acc.w + p.w)
__global__ void k_mid() {
    int i = blockIdx.x * blockDim.x + threadIdx.x;
    if (i >= N_NODES) return;
    float dv = g_dinv[i];
    float4 acc = g_acc[i];
    float4 p   = g_z4[i];
    float z1x = dv * (acc.x + p.x);
    float z1y = dv * (acc.y + p.y);
    float z1z = dv * (acc.z + p.z);
    g_a1[i]  = dv * (acc.w + p.w);
    g_z14[i] = make_float4(dv * z1x, dv * z1y, dv * z1z, 0.0f);   // q = (dinv*z1, 0)
    g_acc[i] = make_float4(0.0f, 0.0f, 0.0f, 0.0f);               // reset for pass 2
}

// ---------------- K5: edge pass 2 — identical form -------------------------
__global__ void k_scatter2() {
    int e = blockIdx.x * blockDim.x + threadIdx.x;
    if (e >= N_EDGES) return;
    int2 sd = load_edge_g(e);
    if ((unsigned)sd.x >= N_NODES || (unsigned)sd.y >= N_NODES) return;
    atomicAdd(&g_acc[sd.y], g_z14[sd.x]);             // acc_d += (dinv_s*z1_s, 0)
}

// ---------------- K6: emit output + restore zero-state for next replay -----
// out = dinv*(acc.xyz + q.xyz) + a1*v + c
__global__ void k_final(float* __restrict__ out) {
    int i = blockIdx.x * blockDim.x + threadIdx.x;
    if (i >= N_NODES) return;
    float dv = g_dinv[i];
    float4 acc = g_acc[i];
    float4 q   = g_z14[i];
    float a    = g_a1[i];
    out[3 * i + 0] = dv * (acc.x + q.x) + a * g_v[0] + g_c[0];
    out[3 * i + 1] = dv * (acc.y + q.y) + a * g_v[1] + g_c[1];
    out[3 * i + 2] = dv * (acc.z + q.z) + a * g_v[2] + g_c[2];
    g_deg[i] = 0.0f;                                  // restore invariant
    g_acc[i] = make_float4(0.0f, 0.0f, 0.0f, 0.0f);
}

// ---------------- launch ----------------
extern "C" void kernel_launch(void* const* d_in, const int* in_sizes, int n_in,
                              void* d_out, int out_size) {
    // ---- size-based scan (order-independent) ----
    const void* cand16[2] = {0, 0}; int n16 = 0;      // feature / edge_index
    const float* W16k[2]  = {0, 0}; int nW  = 0;      // 128x128 mats, in order seen
    const float* b128[3]  = {0, 0, 0}; int nb = 0;    // biases (zeros in data)
    const float* Win  = 0;
    const float* Wout = 0;
    const float* bout = 0;
    int pos3 = -1;

    for (int i = 0; i < n_in; i++) {
        switch (in_sizes[i]) {
            case 1600000: if (n16 < 2) cand16[n16++] = d_in[i]; break;
            case 800000:  /* edge_type — unused */              break;
            case 2048:    Win  = (const float*)d_in[i];         break;
            case 16384:   if (nW < 2) W16k[nW++] = (const float*)d_in[i]; break;
            case 384:     Wout = (const float*)d_in[i];         break;
            case 128:     if (nb < 3) b128[nb++] = (const float*)d_in[i]; break;
            case 3:       bout = (const float*)d_in[i]; pos3 = i; break;
            default: break;
        }
    }
    const float* W1;
    const float* W2;
    if (pos3 == 0) { W2 = W16k[0]; W1 = W16k[1]; }    // reversed-order convention
    else           { W1 = W16k[0]; W2 = W16k[1]; }
    if (n16 < 2 || nW < 2 || nb < 3 || !Win || !Wout || !bout) {   // dict-order fallback
        cand16[0] = d_in[0]; cand16[1] = d_in[1];
        Win = (const float*)d_in[3]; b128[0] = (const float*)d_in[4];
        W1  = (const float*)d_in[5]; b128[1] = (const float*)d_in[6];
        W2  = (const float*)d_in[7]; b128[2] = (const float*)d_in[8];
        Wout = (const float*)d_in[9]; bout = (const float*)d_in[10];
    }
    const float* bin = b128[0];
    const float* b1  = b128[1];
    const float* b2  = b128[2];
    float* out = (float*)d_out;

    const int TB  = 256;
    const int GN  = (N_NODES + TB - 1) / TB;           // 391
    const int GE  = (N_EDGES + TB - 1) / TB;           // 3125
    const int GE2 = (N_EDGES + 383) / 384;             // 2084 edge blocks @384

    k_count<<<GE2 + 1, 384>>>(GE2, (const int*)cand16[0], (const int*)cand16[1],
                              W1, W2, Wout, b1, b2, bout);
    k_feat<<<GN, TB>>>(Win, bin);
    k_scatter1<<<GE, TB>>>();
    k_mid<<<GN, TB>>>();
    k_scatter2<<<GE, TB>>>();
    k_final<<<GN, TB>>>(out);
}